// round 8
// baseline (speedup 1.0000x reference)
#include <cuda_runtime.h>
#include <cuda_bf16.h>
#include <cstdint>
#include <cstddef>

// ============================================================
// ROI classifier head = 3-layer MLP (sort/unsort is identity:
// batch_indices is pre-sorted).
//   L1: relu(X[2048,12544] @ W1[12544,1024] + b1)
//   L2: relu(h1 @ W2[1024,1024] + b2)
//   L3: h2 @ Wc[1024,81] + bc
// L1/L2 via mma.sync m16n8k16 bf16 (legacy HMMA; tcgen05 not
// available under the compute_103 PTX target), bf16x2 split:
// a*b ~= ah*bh + ah*bl + al*bh  (fp32-grade precision).
// R7 = R5 proven core + occupancy fix only:
//   BN 128->64 (grid 256), warp tile 32x32, smem 61440 B,
//   __launch_bounds__(256,2) -> 2 CTAs/SM.
// ============================================================

#define MROWS 2048
#define KFEAT 12544
#define HID   1024
#define NCLS  81

#define BM 128
#define BN 64
#define BK 32
#define NTHREADS 256
#define PADK 40                          // smem row pitch in bf16 (80 B)
#define ATILE_P (128 * PADK * 2)         // 10240 B
#define BTILE_P (64 * PADK * 2)          // 5120 B
#define STAGE_BYTES (2*ATILE_P + 2*BTILE_P)   // 30720
#define SMEM_TOTAL  (2 * STAGE_BYTES)         // 61440 (double buffer)

// -------- scratch (device globals; no allocation allowed) --------
__device__ __align__(128) __nv_bfloat16 g_Xh[MROWS * KFEAT];
__device__ __align__(128) __nv_bfloat16 g_Xl[MROWS * KFEAT];
__device__ __align__(128) __nv_bfloat16 g_W1h[HID * KFEAT];   // [N,K] = W1^T
__device__ __align__(128) __nv_bfloat16 g_W1l[HID * KFEAT];
__device__ __align__(128) __nv_bfloat16 g_W2h[HID * HID];     // [N,K] = W2^T
__device__ __align__(128) __nv_bfloat16 g_W2l[HID * HID];
__device__ __align__(128) __nv_bfloat16 g_B1h[MROWS * HID];
__device__ __align__(128) __nv_bfloat16 g_B1l[MROWS * HID];
__device__ __align__(128) __nv_bfloat16 g_B2h[MROWS * HID];
__device__ __align__(128) __nv_bfloat16 g_B2l[MROWS * HID];

// -------- helpers --------
__device__ __forceinline__ void cp_async16(void* dst_smem, const void* src) {
    uint32_t a;
    asm("{ .reg .u64 t; cvta.to.shared.u64 t, %1; cvt.u32.u64 %0, t; }"
        : "=r"(a) : "l"(dst_smem));
    asm volatile("cp.async.cg.shared.global [%0], [%1], 16;" :: "r"(a), "l"(src) : "memory");
}
__device__ __forceinline__ void cp_commit() {
    asm volatile("cp.async.commit_group;" ::: "memory");
}
template <int N> __device__ __forceinline__ void cp_wait() {
    asm volatile("cp.async.wait_group %0;" :: "n"(N) : "memory");
}
__device__ __forceinline__ void mma16816(float* c, const uint32_t* a, const uint32_t* b) {
    asm volatile(
        "mma.sync.aligned.m16n8k16.row.col.f32.bf16.bf16.f32 "
        "{%0,%1,%2,%3}, {%4,%5,%6,%7}, {%8,%9}, {%0,%1,%2,%3};"
        : "+f"(c[0]), "+f"(c[1]), "+f"(c[2]), "+f"(c[3])
        : "r"(a[0]), "r"(a[1]), "r"(a[2]), "r"(a[3]), "r"(b[0]), "r"(b[1]));
}
__device__ __forceinline__ void split2(float v, __nv_bfloat16& h, __nv_bfloat16& l) {
    h = __float2bfloat16(v);
    l = __float2bfloat16(v - __bfloat162float(h));
}

// ============================================================
// out = relu(A @ B^T + bias), bf16x2 split, fp32 accum.
// A hi/lo: [M, Ktot] row-major.  B hi/lo: [N, Ktot] row-major.
// Output written as bf16 hi/lo, row stride HID.
// ============================================================
__global__ void __launch_bounds__(NTHREADS, 2) mlp_gemm(
    const __nv_bfloat16* __restrict__ Ah, const __nv_bfloat16* __restrict__ Al,
    const __nv_bfloat16* __restrict__ Bh, const __nv_bfloat16* __restrict__ Bl,
    const float* __restrict__ bias,
    __nv_bfloat16* __restrict__ outH, __nv_bfloat16* __restrict__ outL,
    int Ktot)
{
    extern __shared__ char sm[];
    const int tid = threadIdx.x;
    const int bn0 = blockIdx.x * BN;
    const int bm0 = blockIdx.y * BM;

    const int w    = tid >> 5;
    const int m0   = (w >> 1) * 32;      // warps 4(m) x 2(n); warp tile 32x32
    const int n0   = (w & 1) * 32;
    const int lane = tid & 31;
    const int g    = lane >> 2;          // octet row in fragment
    const int t    = lane & 3;

    float acc[2][4][4];
    #pragma unroll
    for (int i = 0; i < 2; i++)
        #pragma unroll
        for (int j = 0; j < 4; j++)
            #pragma unroll
            for (int q = 0; q < 4; q++) acc[i][j][q] = 0.f;

    auto load_stage = [&](int kt, int s) {
        char* base = sm + s * STAGE_BYTES;
        // A tiles (hi/lo): 2 x 128 rows x 4 16B-chunks = 1024 chunks
        #pragma unroll
        for (int u = 0; u < 4; u++) {
            const int q  = u * 256 + tid;          // 0..1023
            const int hl = q >> 9;                 // 0: hi, 1: lo
            const int r  = (q >> 2) & 127;
            const int kc = q & 3;
            const __nv_bfloat16* src = (hl ? Al : Ah)
                + (size_t)(bm0 + r) * Ktot + kt + kc * 8;
            cp_async16(base + hl * ATILE_P + r * (PADK * 2) + kc * 16, src);
        }
        // B tiles (hi/lo): 2 x 64 rows x 4 chunks = 512 chunks
        #pragma unroll
        for (int u = 0; u < 2; u++) {
            const int q  = u * 256 + tid;          // 0..511
            const int hl = q >> 8;
            const int r  = (q >> 2) & 63;
            const int kc = q & 3;
            const __nv_bfloat16* src = (hl ? Bl : Bh)
                + (size_t)(bn0 + r) * Ktot + kt + kc * 8;
            cp_async16(base + 2 * ATILE_P + hl * BTILE_P + r * (PADK * 2) + kc * 16, src);
        }
        cp_commit();
    };

    const int nT = Ktot / BK;
    load_stage(0, 0);

    for (int it = 0; it < nT; it++) {
        const int cur = it & 1;
        if (it + 1 < nT) {
            load_stage((it + 1) * BK, cur ^ 1);
            cp_wait<1>();
        } else {
            cp_wait<0>();
        }
        __syncthreads();

        const char* sAh = sm + cur * STAGE_BYTES;
        const char* sAl = sAh + ATILE_P;
        const char* sBh = sAh + 2 * ATILE_P;
        const char* sBl = sAh + 2 * ATILE_P + BTILE_P;

        #pragma unroll
        for (int ks = 0; ks < 2; ks++) {          // two k16 steps in BK=32
            const int kb = ks * 16;
            uint32_t aH[2][4], aL[2][4], bH[4][2], bL[4][2];
            #pragma unroll
            for (int i = 0; i < 2; i++) {
                const int r  = m0 + i * 16 + g;
                const int o0 = r * (PADK * 2) + (kb + 2 * t) * 2;
                const int o8 = o0 + 8 * (PADK * 2);
                aH[i][0] = *(const uint32_t*)(sAh + o0);
                aH[i][1] = *(const uint32_t*)(sAh + o8);
                aH[i][2] = *(const uint32_t*)(sAh + o0 + 16);
                aH[i][3] = *(const uint32_t*)(sAh + o8 + 16);
                aL[i][0] = *(const uint32_t*)(sAl + o0);
                aL[i][1] = *(const uint32_t*)(sAl + o8);
                aL[i][2] = *(const uint32_t*)(sAl + o0 + 16);
                aL[i][3] = *(const uint32_t*)(sAl + o8 + 16);
            }
            #pragma unroll
            for (int j = 0; j < 4; j++) {
                const int r  = n0 + j * 8 + g;
                const int o0 = r * (PADK * 2) + (kb + 2 * t) * 2;
                bH[j][0] = *(const uint32_t*)(sBh + o0);
                bH[j][1] = *(const uint32_t*)(sBh + o0 + 16);
                bL[j][0] = *(const uint32_t*)(sBl + o0);
                bL[j][1] = *(const uint32_t*)(sBl + o0 + 16);
            }
            // 3 split terms, grouped so each acc has 8 MMAs between reuses
            #pragma unroll
            for (int i = 0; i < 2; i++)
                #pragma unroll
                for (int j = 0; j < 4; j++) mma16816(acc[i][j], aH[i], bH[j]);
            #pragma unroll
            for (int i = 0; i < 2; i++)
                #pragma unroll
                for (int j = 0; j < 4; j++) mma16816(acc[i][j], aH[i], bL[j]);
            #pragma unroll
            for (int i = 0; i < 2; i++)
                #pragma unroll
                for (int j = 0; j < 4; j++) mma16816(acc[i][j], aL[i], bH[j]);
        }
        __syncthreads();
    }

    // epilogue: bias + relu + bf16 hi/lo split, direct global store
    #pragma unroll
    for (int i = 0; i < 2; i++) {
        const int r0 = bm0 + m0 + i * 16 + g;
        #pragma unroll
        for (int j = 0; j < 4; j++) {
            const int col = bn0 + n0 + j * 8 + 2 * t;
            const float bia0 = bias[col], bia1 = bias[col + 1];
            #pragma unroll
            for (int half = 0; half < 2; half++) {
                const int r = r0 + half * 8;
                float v0 = fmaxf(acc[i][j][2 * half]     + bia0, 0.f);
                float v1 = fmaxf(acc[i][j][2 * half + 1] + bia1, 0.f);
                __nv_bfloat16 h0, l0, h1, l1;
                split2(v0, h0, l0); split2(v1, h1, l1);
                __nv_bfloat162 hh; hh.x = h0; hh.y = h1;
                __nv_bfloat162 ll; ll.x = l0; ll.y = l1;
                *reinterpret_cast<__nv_bfloat162*>(outH + (size_t)r * HID + col) = hh;
                *reinterpret_cast<__nv_bfloat162*>(outL + (size_t)r * HID + col) = ll;
            }
        }
    }
}

// ---------------- conversion kernels ----------------
__global__ void split_kernel(const float4* __restrict__ src,
                             __nv_bfloat162* __restrict__ h,
                             __nv_bfloat162* __restrict__ l, long n4)
{
    long i = blockIdx.x * (long)blockDim.x + threadIdx.x;
    const long stride = (long)gridDim.x * blockDim.x;
    for (; i < n4; i += stride) {
        float4 v = src[i];
        __nv_bfloat16 ha, la, hb, lb, hc, lc, hd, ld;
        split2(v.x, ha, la); split2(v.y, hb, lb);
        split2(v.z, hc, lc); split2(v.w, hd, ld);
        __nv_bfloat162 p0, p1, q0, q1;
        p0.x = ha; p0.y = hb; p1.x = hc; p1.y = hd;
        q0.x = la; q0.y = lb; q1.x = lc; q1.y = ld;
        h[2 * i] = p0; h[2 * i + 1] = p1;
        l[2 * i] = q0; l[2 * i + 1] = q1;
    }
}

// W[K,N] fp32 -> Th/Tl[N,K] bf16 (transpose + split)
__global__ void __launch_bounds__(256) transpose_split(
    const float* __restrict__ W, __nv_bfloat16* __restrict__ Th,
    __nv_bfloat16* __restrict__ Tl, int K, int N)
{
    __shared__ float tile[32][33];
    const int n0 = blockIdx.x * 32, k0 = blockIdx.y * 32;
    const int tx = threadIdx.x, ty = threadIdx.y;   // 32 x 8
    #pragma unroll
    for (int r = ty; r < 32; r += 8)
        tile[r][tx] = W[(size_t)(k0 + r) * N + n0 + tx];
    __syncthreads();
    #pragma unroll
    for (int r = ty; r < 32; r += 8) {
        float v = tile[tx][r];                       // = W[k0+tx][n0+r]
        __nv_bfloat16 h, l;
        split2(v, h, l);
        const size_t o = (size_t)(n0 + r) * K + k0 + tx;
        Th[o] = h; Tl[o] = l;
    }
}

// ---------------- final small GEMM (N=81) ----------------
__global__ void __launch_bounds__(128) gemm_cls(
    const __nv_bfloat16* __restrict__ Ah, const __nv_bfloat16* __restrict__ Al,
    const float* __restrict__ Wc, const float* __restrict__ bc,
    float* __restrict__ out)
{
    __shared__ float xs[HID];
    const int row = blockIdx.x;
    const size_t ro = (size_t)row * HID;
    for (int i = threadIdx.x; i < HID; i += 128)
        xs[i] = __bfloat162float(Ah[ro + i]) + __bfloat162float(Al[ro + i]);
    __syncthreads();
    const int c = threadIdx.x;
    if (c < NCLS) {
        float a0 = 0.f, a1 = 0.f, a2 = 0.f, a3 = 0.f;   // break FMA chain
        #pragma unroll 4
        for (int k = 0; k < HID; k += 4) {
            a0 = fmaf(xs[k],     Wc[(size_t)k * NCLS + c],       a0);
            a1 = fmaf(xs[k + 1], Wc[(size_t)(k + 1) * NCLS + c], a1);
            a2 = fmaf(xs[k + 2], Wc[(size_t)(k + 2) * NCLS + c], a2);
            a3 = fmaf(xs[k + 3], Wc[(size_t)(k + 3) * NCLS + c], a3);
        }
        out[(size_t)row * NCLS + c] = bc[c] + ((a0 + a1) + (a2 + a3));
    }
}

// ---------------- launcher ----------------
extern "C" void kernel_launch(void* const* d_in, const int* in_sizes, int n_in,
                              void* d_out, int out_size)
{
    const float* X  = (const float*)d_in[0];
    // d_in[1] = batch_indices (sorted -> identity permutation; unused)
    const float* W1 = (const float*)d_in[2];
    const float* b1 = (const float*)d_in[3];
    const float* W2 = (const float*)d_in[4];
    const float* b2 = (const float*)d_in[5];
    const float* Wc = (const float*)d_in[6];
    const float* bc = (const float*)d_in[7];
    float* out = (float*)d_out;

    __nv_bfloat16 *Xh, *Xl, *W1h, *W1l, *W2h, *W2l, *B1h, *B1l, *B2h, *B2l;
    cudaGetSymbolAddress((void**)&Xh,  g_Xh);  cudaGetSymbolAddress((void**)&Xl,  g_Xl);
    cudaGetSymbolAddress((void**)&W1h, g_W1h); cudaGetSymbolAddress((void**)&W1l, g_W1l);
    cudaGetSymbolAddress((void**)&W2h, g_W2h); cudaGetSymbolAddress((void**)&W2l, g_W2l);
    cudaGetSymbolAddress((void**)&B1h, g_B1h); cudaGetSymbolAddress((void**)&B1l, g_B1l);
    cudaGetSymbolAddress((void**)&B2h, g_B2h); cudaGetSymbolAddress((void**)&B2l, g_B2l);

    cudaFuncSetAttribute(mlp_gemm, cudaFuncAttributeMaxDynamicSharedMemorySize, SMEM_TOTAL);

    // 1) input / weight conversion to bf16 hi/lo
    split_kernel<<<2048, 256>>>((const float4*)X, (__nv_bfloat162*)Xh,
                                (__nv_bfloat162*)Xl, (long)MROWS * KFEAT / 4);
    transpose_split<<<dim3(HID / 32, KFEAT / 32), dim3(32, 8)>>>(W1, W1h, W1l, KFEAT, HID);
    transpose_split<<<dim3(HID / 32, HID / 32),  dim3(32, 8)>>>(W2, W2h, W2l, HID, HID);

    // 2) GEMM1: [2048,12544] x [12544,1024]^T
    mlp_gemm<<<dim3(HID / BN, MROWS / BM), NTHREADS, SMEM_TOTAL>>>(
        Xh, Xl, W1h, W1l, b1, B1h, B1l, KFEAT);

    // 3) GEMM2: [2048,1024] x [1024,1024]^T
    mlp_gemm<<<dim3(HID / BN, MROWS / BM), NTHREADS, SMEM_TOTAL>>>(
        B1h, B1l, W2h, W2l, b2, B2h, B2l, HID);

    // 4) classifier
    gemm_cls<<<MROWS, 128>>>(B2h, B2l, Wc, bc, out);
}

// round 11
// speedup vs baseline: 1.0558x; 1.0558x over previous
#include <cuda_runtime.h>
#include <cuda_bf16.h>
#include <cstdint>
#include <cstddef>

// ============================================================
// ROI classifier head = 3-layer MLP (sort/unsort is identity:
// batch_indices is pre-sorted).
//   L1: relu(X[2048,12544] @ W1[12544,1024] + b1)
//   L2: relu(h1 @ W2[1024,1024] + b2)
//   L3: h2 @ Wc[1024,81] + bc
// L1/L2 via mma.sync m16n8k16 bf16 (legacy HMMA; tcgen05 not
// available under the compute_103 PTX target), bf16x2 split:
// a*b ~= ah*bh + ah*bl + al*bh  (fp32-grade precision).
// R10 = R9 resubmitted (previous round died to a container/infra
// failure before any bench ran). Fragment double-buffer pipeline
// with the cp.async visibility race fixed: every cross-stage
// fragment read sits AFTER cp_wait + __syncthreads.
// ============================================================

#define MROWS 2048
#define KFEAT 12544
#define HID   1024
#define NCLS  81

#define BM 128
#define BN 64
#define BK 32
#define NTHREADS 256
#define PADK 40                          // smem row pitch in bf16 (80 B)
#define ATILE_P (128 * PADK * 2)         // 10240 B
#define BTILE_P (64 * PADK * 2)          // 5120 B
#define STAGE_BYTES (2*ATILE_P + 2*BTILE_P)   // 30720
#define NSTAGE 3
#define SMEM_TOTAL  (NSTAGE * STAGE_BYTES)    // 92160

// -------- scratch (device globals; no allocation allowed) --------
__device__ __align__(128) __nv_bfloat16 g_Xh[MROWS * KFEAT];
__device__ __align__(128) __nv_bfloat16 g_Xl[MROWS * KFEAT];
__device__ __align__(128) __nv_bfloat16 g_W1h[HID * KFEAT];   // [N,K] = W1^T
__device__ __align__(128) __nv_bfloat16 g_W1l[HID * KFEAT];
__device__ __align__(128) __nv_bfloat16 g_W2h[HID * HID];     // [N,K] = W2^T
__device__ __align__(128) __nv_bfloat16 g_W2l[HID * HID];
__device__ __align__(128) __nv_bfloat16 g_B1h[MROWS * HID];
__device__ __align__(128) __nv_bfloat16 g_B1l[MROWS * HID];
__device__ __align__(128) __nv_bfloat16 g_B2h[MROWS * HID];
__device__ __align__(128) __nv_bfloat16 g_B2l[MROWS * HID];

// -------- helpers --------
__device__ __forceinline__ void cp_async16(void* dst_smem, const void* src) {
    uint32_t a;
    asm("{ .reg .u64 t; cvta.to.shared.u64 t, %1; cvt.u32.u64 %0, t; }"
        : "=r"(a) : "l"(dst_smem));
    asm volatile("cp.async.cg.shared.global [%0], [%1], 16;" :: "r"(a), "l"(src) : "memory");
}
__device__ __forceinline__ void cp_commit() {
    asm volatile("cp.async.commit_group;" ::: "memory");
}
template <int N> __device__ __forceinline__ void cp_wait() {
    asm volatile("cp.async.wait_group %0;" :: "n"(N) : "memory");
}
__device__ __forceinline__ void mma16816(float* c, const uint32_t* a, const uint32_t* b) {
    asm volatile(
        "mma.sync.aligned.m16n8k16.row.col.f32.bf16.bf16.f32 "
        "{%0,%1,%2,%3}, {%4,%5,%6,%7}, {%8,%9}, {%0,%1,%2,%3};"
        : "+f"(c[0]), "+f"(c[1]), "+f"(c[2]), "+f"(c[3])
        : "r"(a[0]), "r"(a[1]), "r"(a[2]), "r"(a[3]), "r"(b[0]), "r"(b[1]));
}
__device__ __forceinline__ void split2(float v, __nv_bfloat16& h, __nv_bfloat16& l) {
    h = __float2bfloat16(v);
    l = __float2bfloat16(v - __bfloat162float(h));
}

// fragment set for one k16 step
struct Frag {
    uint32_t aH[2][4], aL[2][4], bH[4][2], bL[4][2];
};

// ============================================================
// out = relu(A @ B^T + bias), bf16x2 split, fp32 accum.
// A hi/lo: [M, Ktot] row-major.  B hi/lo: [N, Ktot] row-major.
// Output written as bf16 hi/lo, row stride HID.
// ============================================================
__global__ void __launch_bounds__(NTHREADS, 2) mlp_gemm(
    const __nv_bfloat16* __restrict__ Ah, const __nv_bfloat16* __restrict__ Al,
    const __nv_bfloat16* __restrict__ Bh, const __nv_bfloat16* __restrict__ Bl,
    const float* __restrict__ bias,
    __nv_bfloat16* __restrict__ outH, __nv_bfloat16* __restrict__ outL,
    int Ktot)
{
    extern __shared__ char sm[];
    const int tid = threadIdx.x;
    const int bn0 = blockIdx.x * BN;
    const int bm0 = blockIdx.y * BM;

    const int w    = tid >> 5;
    const int m0   = (w >> 1) * 32;      // warps 4(m) x 2(n); warp tile 32x32
    const int n0   = (w & 1) * 32;
    const int lane = tid & 31;
    const int g    = lane >> 2;
    const int t    = lane & 3;

    float acc[2][4][4];
    #pragma unroll
    for (int i = 0; i < 2; i++)
        #pragma unroll
        for (int j = 0; j < 4; j++)
            #pragma unroll
            for (int q = 0; q < 4; q++) acc[i][j][q] = 0.f;

    auto load_stage = [&](int kt, int s) {
        char* base = sm + s * STAGE_BYTES;
        #pragma unroll
        for (int u = 0; u < 4; u++) {            // A hi/lo: 1024 16B chunks
            const int q  = u * 256 + tid;
            const int hl = q >> 9;
            const int r  = (q >> 2) & 127;
            const int kc = q & 3;
            const __nv_bfloat16* src = (hl ? Al : Ah)
                + (size_t)(bm0 + r) * Ktot + kt + kc * 8;
            cp_async16(base + hl * ATILE_P + r * (PADK * 2) + kc * 16, src);
        }
        #pragma unroll
        for (int u = 0; u < 2; u++) {            // B hi/lo: 512 16B chunks
            const int q  = u * 256 + tid;
            const int hl = q >> 8;
            const int r  = (q >> 2) & 63;
            const int kc = q & 3;
            const __nv_bfloat16* src = (hl ? Bl : Bh)
                + (size_t)(bn0 + r) * Ktot + kt + kc * 8;
            cp_async16(base + 2 * ATILE_P + hl * BTILE_P + r * (PADK * 2) + kc * 16, src);
        }
        cp_commit();
    };

    auto load_frags = [&](Frag& f, const char* stg, int ks) {
        const char* sAh = stg;
        const char* sAl = stg + ATILE_P;
        const char* sBh = stg + 2 * ATILE_P;
        const char* sBl = stg + 2 * ATILE_P + BTILE_P;
        const int kb = ks * 16;
        #pragma unroll
        for (int i = 0; i < 2; i++) {
            const int r  = m0 + i * 16 + g;
            const int o0 = r * (PADK * 2) + (kb + 2 * t) * 2;
            const int o8 = o0 + 8 * (PADK * 2);
            f.aH[i][0] = *(const uint32_t*)(sAh + o0);
            f.aH[i][1] = *(const uint32_t*)(sAh + o8);
            f.aH[i][2] = *(const uint32_t*)(sAh + o0 + 16);
            f.aH[i][3] = *(const uint32_t*)(sAh + o8 + 16);
            f.aL[i][0] = *(const uint32_t*)(sAl + o0);
            f.aL[i][1] = *(const uint32_t*)(sAl + o8);
            f.aL[i][2] = *(const uint32_t*)(sAl + o0 + 16);
            f.aL[i][3] = *(const uint32_t*)(sAl + o8 + 16);
        }
        #pragma unroll
        for (int j = 0; j < 4; j++) {
            const int r  = n0 + j * 8 + g;
            const int o0 = r * (PADK * 2) + (kb + 2 * t) * 2;
            f.bH[j][0] = *(const uint32_t*)(sBh + o0);
            f.bH[j][1] = *(const uint32_t*)(sBh + o0 + 16);
            f.bL[j][0] = *(const uint32_t*)(sBl + o0);
            f.bL[j][1] = *(const uint32_t*)(sBl + o0 + 16);
        }
    };

    auto run_mmas = [&](const Frag& f) {
        #pragma unroll
        for (int i = 0; i < 2; i++)
            #pragma unroll
            for (int j = 0; j < 4; j++) mma16816(acc[i][j], f.aH[i], f.bH[j]);
        #pragma unroll
        for (int i = 0; i < 2; i++)
            #pragma unroll
            for (int j = 0; j < 4; j++) mma16816(acc[i][j], f.aH[i], f.bL[j]);
        #pragma unroll
        for (int i = 0; i < 2; i++)
            #pragma unroll
            for (int j = 0; j < 4; j++) mma16816(acc[i][j], f.aL[i], f.bH[j]);
    };

    const int nT = Ktot / BK;

    // prologue: fill stages 0 and 1; make stage 0 visible; preload f0
    load_stage(0, 0);
    load_stage(BK, 1);
    cp_wait<1>();            // own stage-0 copies done
    __syncthreads();         // everyone's stage-0 copies visible
    Frag f0, f1;
    load_frags(f0, sm, 0);

    for (int it = 0; it < nT; it++) {
        const char* stg = sm + (it % NSTAGE) * STAGE_BYTES;

        // first half: ks=1 frag prefetch overlaps MMAs on f0 (ks=0)
        load_frags(f1, stg, 1);              // stage it — visible since prev barrier
        run_mmas(f0);

        // refill ring slot (it+2)%3 == (it-1)%3; its last reads were
        // before the previous iteration's barrier -> safe to overwrite
        if (it + 2 < nT) load_stage((it + 2) * BK, (it + 2) % NSTAGE);
        else cp_commit();                    // keep group accounting uniform

        cp_wait<1>();                        // own stage it+1 copies done
        __syncthreads();                     // ALL threads' stage it+1 visible

        // second half: next iter's ks=0 frag prefetch overlaps MMAs on f1
        if (it + 1 < nT)
            load_frags(f0, sm + ((it + 1) % NSTAGE) * STAGE_BYTES, 0);
        run_mmas(f1);
    }

    // epilogue: bias + relu + bf16 hi/lo split, direct global store
    #pragma unroll
    for (int i = 0; i < 2; i++) {
        const int r0 = bm0 + m0 + i * 16 + g;
        #pragma unroll
        for (int j = 0; j < 4; j++) {
            const int col = bn0 + n0 + j * 8 + 2 * t;
            const float bia0 = bias[col], bia1 = bias[col + 1];
            #pragma unroll
            for (int half = 0; half < 2; half++) {
                const int r = r0 + half * 8;
                float v0 = fmaxf(acc[i][j][2 * half]     + bia0, 0.f);
                float v1 = fmaxf(acc[i][j][2 * half + 1] + bia1, 0.f);
                __nv_bfloat16 h0, l0, h1, l1;
                split2(v0, h0, l0); split2(v1, h1, l1);
                __nv_bfloat162 hh; hh.x = h0; hh.y = h1;
                __nv_bfloat162 ll; ll.x = l0; ll.y = l1;
                *reinterpret_cast<__nv_bfloat162*>(outH + (size_t)r * HID + col) = hh;
                *reinterpret_cast<__nv_bfloat162*>(outL + (size_t)r * HID + col) = ll;
            }
        }
    }
}

// ---------------- conversion kernels ----------------
__global__ void split_kernel(const float4* __restrict__ src,
                             __nv_bfloat162* __restrict__ h,
                             __nv_bfloat162* __restrict__ l, long n4)
{
    long i = blockIdx.x * (long)blockDim.x + threadIdx.x;
    const long stride = (long)gridDim.x * blockDim.x;
    for (; i < n4; i += stride) {
        float4 v = src[i];
        __nv_bfloat16 ha, la, hb, lb, hc, lc, hd, ld;
        split2(v.x, ha, la); split2(v.y, hb, lb);
        split2(v.z, hc, lc); split2(v.w, hd, ld);
        __nv_bfloat162 p0, p1, q0, q1;
        p0.x = ha; p0.y = hb; p1.x = hc; p1.y = hd;
        q0.x = la; q0.y = lb; q1.x = lc; q1.y = ld;
        h[2 * i] = p0; h[2 * i + 1] = p1;
        l[2 * i] = q0; l[2 * i + 1] = q1;
    }
}

// W[K,N] fp32 -> Th/Tl[N,K] bf16 (transpose + split)
__global__ void __launch_bounds__(256) transpose_split(
    const float* __restrict__ W, __nv_bfloat16* __restrict__ Th,
    __nv_bfloat16* __restrict__ Tl, int K, int N)
{
    __shared__ float tile[32][33];
    const int n0 = blockIdx.x * 32, k0 = blockIdx.y * 32;
    const int tx = threadIdx.x, ty = threadIdx.y;   // 32 x 8
    #pragma unroll
    for (int r = ty; r < 32; r += 8)
        tile[r][tx] = W[(size_t)(k0 + r) * N + n0 + tx];
    __syncthreads();
    #pragma unroll
    for (int r = ty; r < 32; r += 8) {
        float v = tile[tx][r];                       // = W[k0+tx][n0+r]
        __nv_bfloat16 h, l;
        split2(v, h, l);
        const size_t o = (size_t)(n0 + r) * K + k0 + tx;
        Th[o] = h; Tl[o] = l;
    }
}

// ---------------- final small GEMM (N=81) ----------------
// 8 rows per block -> Wc L2 traffic / 8 vs the per-row version.
#define CLS_ROWS 8
__global__ void __launch_bounds__(128) gemm_cls(
    const __nv_bfloat16* __restrict__ Ah, const __nv_bfloat16* __restrict__ Al,
    const float* __restrict__ Wc, const float* __restrict__ bc,
    float* __restrict__ out)
{
    __shared__ float xs[HID * CLS_ROWS];   // xs[k*8 + r], 32 KB
    const int row0 = blockIdx.x * CLS_ROWS;
    for (int idx = threadIdx.x; idx < HID * CLS_ROWS; idx += 128) {
        const int r = idx >> 10;           // 0..7
        const int k = idx & (HID - 1);
        const size_t go = (size_t)(row0 + r) * HID + k;
        xs[k * CLS_ROWS + r] = __bfloat162float(Ah[go]) + __bfloat162float(Al[go]);
    }
    __syncthreads();

    const int c = threadIdx.x;
    if (c < NCLS) {
        float a[CLS_ROWS];
        #pragma unroll
        for (int r = 0; r < CLS_ROWS; r++) a[r] = 0.f;
        #pragma unroll 4
        for (int k = 0; k < HID; k++) {
            const float wv = Wc[(size_t)k * NCLS + c];
            const float4 x0 = *reinterpret_cast<const float4*>(&xs[k * CLS_ROWS]);
            const float4 x1 = *reinterpret_cast<const float4*>(&xs[k * CLS_ROWS + 4]);
            a[0] = fmaf(x0.x, wv, a[0]);
            a[1] = fmaf(x0.y, wv, a[1]);
            a[2] = fmaf(x0.z, wv, a[2]);
            a[3] = fmaf(x0.w, wv, a[3]);
            a[4] = fmaf(x1.x, wv, a[4]);
            a[5] = fmaf(x1.y, wv, a[5]);
            a[6] = fmaf(x1.z, wv, a[6]);
            a[7] = fmaf(x1.w, wv, a[7]);
        }
        const float bcv = bc[c];
        #pragma unroll
        for (int r = 0; r < CLS_ROWS; r++)
            out[(size_t)(row0 + r) * NCLS + c] = a[r] + bcv;
    }
}

// ---------------- launcher ----------------
extern "C" void kernel_launch(void* const* d_in, const int* in_sizes, int n_in,
                              void* d_out, int out_size)
{
    const float* X  = (const float*)d_in[0];
    // d_in[1] = batch_indices (sorted -> identity permutation; unused)
    const float* W1 = (const float*)d_in[2];
    const float* b1 = (const float*)d_in[3];
    const float* W2 = (const float*)d_in[4];
    const float* b2 = (const float*)d_in[5];
    const float* Wc = (const float*)d_in[6];
    const float* bc = (const float*)d_in[7];
    float* out = (float*)d_out;

    __nv_bfloat16 *Xh, *Xl, *W1h, *W1l, *W2h, *W2l, *B1h, *B1l, *B2h, *B2l;
    cudaGetSymbolAddress((void**)&Xh,  g_Xh);  cudaGetSymbolAddress((void**)&Xl,  g_Xl);
    cudaGetSymbolAddress((void**)&W1h, g_W1h); cudaGetSymbolAddress((void**)&W1l, g_W1l);
    cudaGetSymbolAddress((void**)&W2h, g_W2h); cudaGetSymbolAddress((void**)&W2l, g_W2l);
    cudaGetSymbolAddress((void**)&B1h, g_B1h); cudaGetSymbolAddress((void**)&B1l, g_B1l);
    cudaGetSymbolAddress((void**)&B2h, g_B2h); cudaGetSymbolAddress((void**)&B2l, g_B2l);

    cudaFuncSetAttribute(mlp_gemm, cudaFuncAttributeMaxDynamicSharedMemorySize, SMEM_TOTAL);

    // 1) input / weight conversion to bf16 hi/lo
    split_kernel<<<2048, 256>>>((const float4*)X, (__nv_bfloat162*)Xh,
                                (__nv_bfloat162*)Xl, (long)MROWS * KFEAT / 4);
    transpose_split<<<dim3(HID / 32, KFEAT / 32), dim3(32, 8)>>>(W1, W1h, W1l, KFEAT, HID);
    transpose_split<<<dim3(HID / 32, HID / 32),  dim3(32, 8)>>>(W2, W2h, W2l, HID, HID);

    // 2) GEMM1: [2048,12544] x [12544,1024]^T
    mlp_gemm<<<dim3(HID / BN, MROWS / BM), NTHREADS, SMEM_TOTAL>>>(
        Xh, Xl, W1h, W1l, b1, B1h, B1l, KFEAT);

    // 3) GEMM2: [2048,1024] x [1024,1024]^T
    mlp_gemm<<<dim3(HID / BN, MROWS / BM), NTHREADS, SMEM_TOTAL>>>(
        B1h, B1l, W2h, W2l, b2, B2h, B2l, HID);

    // 4) classifier
    gemm_cls<<<MROWS / CLS_ROWS, 128>>>(B2h, B2l, Wc, bc, out);
}

// round 12
// speedup vs baseline: 1.2096x; 1.1456x over previous
#include <cuda_runtime.h>
#include <cuda_bf16.h>
#include <cstdint>
#include <cstddef>

// ============================================================
// ROI classifier head = 3-layer MLP (sort/unsort is identity:
// batch_indices is pre-sorted).
//   L1: relu(X[2048,12544] @ W1[12544,1024] + b1)
//   L2: relu(h1 @ W2[1024,1024] + b2)
//   L3: h2 @ Wc[1024,81] + bc
// L1/L2 via mma.sync m16n8k16 bf16 (legacy HMMA; tcgen05 not
// available under the compute_103 PTX target), bf16x2 split:
// a*b ~= ah*bh + ah*bl + al*bh  (fp32-grade precision).
// R11 = R10 with ONE change: fragment feed via ldmatrix.x4
// (8 LDSM per warp-half-step instead of 32 LDS.32) — same bytes,
// 4x fewer issue slots / latency arms, padded pitch stays
// conflict-free (row*20 mod 32 distinct over 8 rows).
// ============================================================

#define MROWS 2048
#define KFEAT 12544
#define HID   1024
#define NCLS  81

#define BM 128
#define BN 64
#define BK 32
#define NTHREADS 256
#define PADK 40                          // smem row pitch in bf16 (80 B)
#define ROWB (PADK * 2)                  // 80 bytes
#define ATILE_P (128 * ROWB)             // 10240 B
#define BTILE_P (64 * ROWB)              // 5120 B
#define STAGE_BYTES (2*ATILE_P + 2*BTILE_P)   // 30720
#define NSTAGE 3
#define SMEM_TOTAL  (NSTAGE * STAGE_BYTES)    // 92160

// -------- scratch (device globals; no allocation allowed) --------
__device__ __align__(128) __nv_bfloat16 g_Xh[MROWS * KFEAT];
__device__ __align__(128) __nv_bfloat16 g_Xl[MROWS * KFEAT];
__device__ __align__(128) __nv_bfloat16 g_W1h[HID * KFEAT];   // [N,K] = W1^T
__device__ __align__(128) __nv_bfloat16 g_W1l[HID * KFEAT];
__device__ __align__(128) __nv_bfloat16 g_W2h[HID * HID];     // [N,K] = W2^T
__device__ __align__(128) __nv_bfloat16 g_W2l[HID * HID];
__device__ __align__(128) __nv_bfloat16 g_B1h[MROWS * HID];
__device__ __align__(128) __nv_bfloat16 g_B1l[MROWS * HID];
__device__ __align__(128) __nv_bfloat16 g_B2h[MROWS * HID];
__device__ __align__(128) __nv_bfloat16 g_B2l[MROWS * HID];

// -------- helpers --------
__device__ __forceinline__ uint32_t smem_u32(const void* p) {
    uint32_t a;
    asm("{ .reg .u64 t; cvta.to.shared.u64 t, %1; cvt.u32.u64 %0, t; }"
        : "=r"(a) : "l"(p));
    return a;
}
__device__ __forceinline__ void cp_async16(void* dst_smem, const void* src) {
    uint32_t a;
    asm("{ .reg .u64 t; cvta.to.shared.u64 t, %1; cvt.u32.u64 %0, t; }"
        : "=r"(a) : "l"(dst_smem));
    asm volatile("cp.async.cg.shared.global [%0], [%1], 16;" :: "r"(a), "l"(src) : "memory");
}
__device__ __forceinline__ void cp_commit() {
    asm volatile("cp.async.commit_group;" ::: "memory");
}
template <int N> __device__ __forceinline__ void cp_wait() {
    asm volatile("cp.async.wait_group %0;" :: "n"(N) : "memory");
}
__device__ __forceinline__ void ldm_x4(uint32_t* r, uint32_t addr) {
    asm volatile("ldmatrix.sync.aligned.m8n8.x4.shared.b16 {%0,%1,%2,%3}, [%4];"
        : "=r"(r[0]), "=r"(r[1]), "=r"(r[2]), "=r"(r[3]) : "r"(addr));
}
__device__ __forceinline__ void mma16816(float* c, const uint32_t* a, const uint32_t* b) {
    asm volatile(
        "mma.sync.aligned.m16n8k16.row.col.f32.bf16.bf16.f32 "
        "{%0,%1,%2,%3}, {%4,%5,%6,%7}, {%8,%9}, {%0,%1,%2,%3};"
        : "+f"(c[0]), "+f"(c[1]), "+f"(c[2]), "+f"(c[3])
        : "r"(a[0]), "r"(a[1]), "r"(a[2]), "r"(a[3]), "r"(b[0]), "r"(b[1]));
}
__device__ __forceinline__ void split2(float v, __nv_bfloat16& h, __nv_bfloat16& l) {
    h = __float2bfloat16(v);
    l = __float2bfloat16(v - __bfloat162float(h));
}

// fragment set for one k16 step
struct Frag {
    uint32_t aH[2][4], aL[2][4], bH[4][2], bL[4][2];
};

// ============================================================
// out = relu(A @ B^T + bias), bf16x2 split, fp32 accum.
// A hi/lo: [M, Ktot] row-major.  B hi/lo: [N, Ktot] row-major.
// Output written as bf16 hi/lo, row stride HID.
// ============================================================
__global__ void __launch_bounds__(NTHREADS, 2) mlp_gemm(
    const __nv_bfloat16* __restrict__ Ah, const __nv_bfloat16* __restrict__ Al,
    const __nv_bfloat16* __restrict__ Bh, const __nv_bfloat16* __restrict__ Bl,
    const float* __restrict__ bias,
    __nv_bfloat16* __restrict__ outH, __nv_bfloat16* __restrict__ outL,
    int Ktot)
{
    extern __shared__ char sm[];
    const uint32_t sb32 = smem_u32(sm);
    const int tid = threadIdx.x;
    const int bn0 = blockIdx.x * BN;
    const int bm0 = blockIdx.y * BM;

    const int w    = tid >> 5;
    const int m0   = (w >> 1) * 32;      // warps 4(m) x 2(n); warp tile 32x32
    const int n0   = (w & 1) * 32;
    const int lane = tid & 31;
    const int g    = lane >> 2;
    const int t    = lane & 3;

    // ldmatrix lane->row/k-half mapping (derived from the fragment layout
    // the scalar-LDS version proves correct):
    //   A: row = m0 + i*16 + (lane&15), k-half = lane>>4
    //   B: row = n0 + jj*16 + (lane&7) + ((lane>>4)<<3), k-half = (lane>>3)&1
    const uint32_t aOff0 = (uint32_t)((m0 + (lane & 15)) * ROWB + ((lane >> 4) << 4));
    const int bRow = (lane & 7) + ((lane >> 4) << 3);
    const uint32_t bOff0 = (uint32_t)((n0 + bRow) * ROWB + (((lane >> 3) & 1) << 4));

    float acc[2][4][4];
    #pragma unroll
    for (int i = 0; i < 2; i++)
        #pragma unroll
        for (int j = 0; j < 4; j++)
            #pragma unroll
            for (int q = 0; q < 4; q++) acc[i][j][q] = 0.f;

    auto load_stage = [&](int kt, int s) {
        char* base = sm + s * STAGE_BYTES;
        #pragma unroll
        for (int u = 0; u < 4; u++) {            // A hi/lo: 1024 16B chunks
            const int q  = u * 256 + tid;
            const int hl = q >> 9;
            const int r  = (q >> 2) & 127;
            const int kc = q & 3;
            const __nv_bfloat16* src = (hl ? Al : Ah)
                + (size_t)(bm0 + r) * Ktot + kt + kc * 8;
            cp_async16(base + hl * ATILE_P + r * ROWB + kc * 16, src);
        }
        #pragma unroll
        for (int u = 0; u < 2; u++) {            // B hi/lo: 512 16B chunks
            const int q  = u * 256 + tid;
            const int hl = q >> 8;
            const int r  = (q >> 2) & 63;
            const int kc = q & 3;
            const __nv_bfloat16* src = (hl ? Bl : Bh)
                + (size_t)(bn0 + r) * Ktot + kt + kc * 8;
            cp_async16(base + 2 * ATILE_P + hl * BTILE_P + r * ROWB + kc * 16, src);
        }
        cp_commit();
    };

    // fragment load via ldmatrix.x4: 8 LDSM per (stage, ks)
    auto load_frags = [&](Frag& f, uint32_t stageOff, int ks) {
        const uint32_t kb = (uint32_t)(ks * 32);           // k16 step -> 32 B
        const uint32_t baseA = sb32 + stageOff;
        #pragma unroll
        for (int i = 0; i < 2; i++) {
            const uint32_t ao = aOff0 + (uint32_t)(i * 16 * ROWB) + kb;
            ldm_x4(f.aH[i], baseA + ao);                    // Ah tile at +0
            ldm_x4(f.aL[i], baseA + ATILE_P + ao);          // Al tile
        }
        const uint32_t baseB = sb32 + stageOff + 2 * ATILE_P;
        #pragma unroll
        for (int jj = 0; jj < 2; jj++) {                    // n 0-15, 16-31
            const uint32_t bo = bOff0 + (uint32_t)(jj * 16 * ROWB) + kb;
            uint32_t v[4];
            ldm_x4(v, baseB + bo);                          // Bh tile
            f.bH[jj * 2][0]     = v[0]; f.bH[jj * 2][1]     = v[1];
            f.bH[jj * 2 + 1][0] = v[2]; f.bH[jj * 2 + 1][1] = v[3];
            ldm_x4(v, baseB + BTILE_P + bo);                // Bl tile
            f.bL[jj * 2][0]     = v[0]; f.bL[jj * 2][1]     = v[1];
            f.bL[jj * 2 + 1][0] = v[2]; f.bL[jj * 2 + 1][1] = v[3];
        }
    };

    auto run_mmas = [&](const Frag& f) {
        #pragma unroll
        for (int i = 0; i < 2; i++)
            #pragma unroll
            for (int j = 0; j < 4; j++) mma16816(acc[i][j], f.aH[i], f.bH[j]);
        #pragma unroll
        for (int i = 0; i < 2; i++)
            #pragma unroll
            for (int j = 0; j < 4; j++) mma16816(acc[i][j], f.aH[i], f.bL[j]);
        #pragma unroll
        for (int i = 0; i < 2; i++)
            #pragma unroll
            for (int j = 0; j < 4; j++) mma16816(acc[i][j], f.aL[i], f.bH[j]);
    };

    const int nT = Ktot / BK;

    // prologue: fill stages 0 and 1; make stage 0 visible; preload f0
    load_stage(0, 0);
    load_stage(BK, 1);
    cp_wait<1>();            // own stage-0 copies done
    __syncthreads();         // everyone's stage-0 copies visible
    Frag f0, f1;
    load_frags(f0, 0, 0);

    for (int it = 0; it < nT; it++) {
        const uint32_t stgOff = (uint32_t)((it % NSTAGE) * STAGE_BYTES);

        // first half: ks=1 frag prefetch overlaps MMAs on f0 (ks=0)
        load_frags(f1, stgOff, 1);           // stage it — visible since prev barrier
        run_mmas(f0);

        // refill ring slot (it+2)%3 == (it-1)%3; its last reads were
        // before the previous iteration's barrier -> safe to overwrite
        if (it + 2 < nT) load_stage((it + 2) * BK, (it + 2) % NSTAGE);
        else cp_commit();                    // keep group accounting uniform

        cp_wait<1>();                        // own stage it+1 copies done
        __syncthreads();                     // ALL threads' stage it+1 visible

        // second half: next iter's ks=0 frag prefetch overlaps MMAs on f1
        if (it + 1 < nT)
            load_frags(f0, (uint32_t)(((it + 1) % NSTAGE) * STAGE_BYTES), 0);
        run_mmas(f1);
    }

    // epilogue: bias + relu + bf16 hi/lo split, direct global store
    #pragma unroll
    for (int i = 0; i < 2; i++) {
        const int r0 = bm0 + m0 + i * 16 + g;
        #pragma unroll
        for (int j = 0; j < 4; j++) {
            const int col = bn0 + n0 + j * 8 + 2 * t;
            const float bia0 = bias[col], bia1 = bias[col + 1];
            #pragma unroll
            for (int half = 0; half < 2; half++) {
                const int r = r0 + half * 8;
                float v0 = fmaxf(acc[i][j][2 * half]     + bia0, 0.f);
                float v1 = fmaxf(acc[i][j][2 * half + 1] + bia1, 0.f);
                __nv_bfloat16 h0, l0, h1, l1;
                split2(v0, h0, l0); split2(v1, h1, l1);
                __nv_bfloat162 hh; hh.x = h0; hh.y = h1;
                __nv_bfloat162 ll; ll.x = l0; ll.y = l1;
                *reinterpret_cast<__nv_bfloat162*>(outH + (size_t)r * HID + col) = hh;
                *reinterpret_cast<__nv_bfloat162*>(outL + (size_t)r * HID + col) = ll;
            }
        }
    }
}

// ---------------- conversion kernels ----------------
__global__ void split_kernel(const float4* __restrict__ src,
                             __nv_bfloat162* __restrict__ h,
                             __nv_bfloat162* __restrict__ l, long n4)
{
    long i = blockIdx.x * (long)blockDim.x + threadIdx.x;
    const long stride = (long)gridDim.x * blockDim.x;
    for (; i < n4; i += stride) {
        float4 v = src[i];
        __nv_bfloat16 ha, la, hb, lb, hc, lc, hd, ld;
        split2(v.x, ha, la); split2(v.y, hb, lb);
        split2(v.z, hc, lc); split2(v.w, hd, ld);
        __nv_bfloat162 p0, p1, q0, q1;
        p0.x = ha; p0.y = hb; p1.x = hc; p1.y = hd;
        q0.x = la; q0.y = lb; q1.x = lc; q1.y = ld;
        h[2 * i] = p0; h[2 * i + 1] = p1;
        l[2 * i] = q0; l[2 * i + 1] = q1;
    }
}

// W[K,N] fp32 -> Th/Tl[N,K] bf16 (transpose + split)
__global__ void __launch_bounds__(256) transpose_split(
    const float* __restrict__ W, __nv_bfloat16* __restrict__ Th,
    __nv_bfloat16* __restrict__ Tl, int K, int N)
{
    __shared__ float tile[32][33];
    const int n0 = blockIdx.x * 32, k0 = blockIdx.y * 32;
    const int tx = threadIdx.x, ty = threadIdx.y;   // 32 x 8
    #pragma unroll
    for (int r = ty; r < 32; r += 8)
        tile[r][tx] = W[(size_t)(k0 + r) * N + n0 + tx];
    __syncthreads();
    #pragma unroll
    for (int r = ty; r < 32; r += 8) {
        float v = tile[tx][r];                       // = W[k0+tx][n0+r]
        __nv_bfloat16 h, l;
        split2(v, h, l);
        const size_t o = (size_t)(n0 + r) * K + k0 + tx;
        Th[o] = h; Tl[o] = l;
    }
}

// ---------------- final small GEMM (N=81) ----------------
// 8 rows per block -> Wc L2 traffic / 8 vs the per-row version.
#define CLS_ROWS 8
__global__ void __launch_bounds__(128) gemm_cls(
    const __nv_bfloat16* __restrict__ Ah, const __nv_bfloat16* __restrict__ Al,
    const float* __restrict__ Wc, const float* __restrict__ bc,
    float* __restrict__ out)
{
    __shared__ float xs[HID * CLS_ROWS];   // xs[k*8 + r], 32 KB
    const int row0 = blockIdx.x * CLS_ROWS;
    for (int idx = threadIdx.x; idx < HID * CLS_ROWS; idx += 128) {
        const int r = idx >> 10;           // 0..7
        const int k = idx & (HID - 1);
        const size_t go = (size_t)(row0 + r) * HID + k;
        xs[k * CLS_ROWS + r] = __bfloat162float(Ah[go]) + __bfloat162float(Al[go]);
    }
    __syncthreads();

    const int c = threadIdx.x;
    if (c < NCLS) {
        float a[CLS_ROWS];
        #pragma unroll
        for (int r = 0; r < CLS_ROWS; r++) a[r] = 0.f;
        #pragma unroll 4
        for (int k = 0; k < HID; k++) {
            const float wv = Wc[(size_t)k * NCLS + c];
            const float4 x0 = *reinterpret_cast<const float4*>(&xs[k * CLS_ROWS]);
            const float4 x1 = *reinterpret_cast<const float4*>(&xs[k * CLS_ROWS + 4]);
            a[0] = fmaf(x0.x, wv, a[0]);
            a[1] = fmaf(x0.y, wv, a[1]);
            a[2] = fmaf(x0.z, wv, a[2]);
            a[3] = fmaf(x0.w, wv, a[3]);
            a[4] = fmaf(x1.x, wv, a[4]);
            a[5] = fmaf(x1.y, wv, a[5]);
            a[6] = fmaf(x1.z, wv, a[6]);
            a[7] = fmaf(x1.w, wv, a[7]);
        }
        const float bcv = bc[c];
        #pragma unroll
        for (int r = 0; r < CLS_ROWS; r++)
            out[(size_t)(row0 + r) * NCLS + c] = a[r] + bcv;
    }
}

// ---------------- launcher ----------------
extern "C" void kernel_launch(void* const* d_in, const int* in_sizes, int n_in,
                              void* d_out, int out_size)
{
    const float* X  = (const float*)d_in[0];
    // d_in[1] = batch_indices (sorted -> identity permutation; unused)
    const float* W1 = (const float*)d_in[2];
    const float* b1 = (const float*)d_in[3];
    const float* W2 = (const float*)d_in[4];
    const float* b2 = (const float*)d_in[5];
    const float* Wc = (const float*)d_in[6];
    const float* bc = (const float*)d_in[7];
    float* out = (float*)d_out;

    __nv_bfloat16 *Xh, *Xl, *W1h, *W1l, *W2h, *W2l, *B1h, *B1l, *B2h, *B2l;
    cudaGetSymbolAddress((void**)&Xh,  g_Xh);  cudaGetSymbolAddress((void**)&Xl,  g_Xl);
    cudaGetSymbolAddress((void**)&W1h, g_W1h); cudaGetSymbolAddress((void**)&W1l, g_W1l);
    cudaGetSymbolAddress((void**)&W2h, g_W2h); cudaGetSymbolAddress((void**)&W2l, g_W2l);
    cudaGetSymbolAddress((void**)&B1h, g_B1h); cudaGetSymbolAddress((void**)&B1l, g_B1l);
    cudaGetSymbolAddress((void**)&B2h, g_B2h); cudaGetSymbolAddress((void**)&B2l, g_B2l);

    cudaFuncSetAttribute(mlp_gemm, cudaFuncAttributeMaxDynamicSharedMemorySize, SMEM_TOTAL);

    // 1) input / weight conversion to bf16 hi/lo
    split_kernel<<<2048, 256>>>((const float4*)X, (__nv_bfloat162*)Xh,
                                (__nv_bfloat162*)Xl, (long)MROWS * KFEAT / 4);
    transpose_split<<<dim3(HID / 32, KFEAT / 32), dim3(32, 8)>>>(W1, W1h, W1l, KFEAT, HID);
    transpose_split<<<dim3(HID / 32, HID / 32),  dim3(32, 8)>>>(W2, W2h, W2l, HID, HID);

    // 2) GEMM1: [2048,12544] x [12544,1024]^T
    mlp_gemm<<<dim3(HID / BN, MROWS / BM), NTHREADS, SMEM_TOTAL>>>(
        Xh, Xl, W1h, W1l, b1, B1h, B1l, KFEAT);

    // 3) GEMM2: [2048,1024] x [1024,1024]^T
    mlp_gemm<<<dim3(HID / BN, MROWS / BM), NTHREADS, SMEM_TOTAL>>>(
        B1h, B1l, W2h, W2l, b2, B2h, B2l, HID);

    // 4) classifier
    gemm_cls<<<MROWS / CLS_ROWS, 128>>>(B2h, B2l, Wc, bc, out);
}